// round 2
// baseline (speedup 1.0000x reference)
#include <cuda_runtime.h>

#define NB 16384
#define LN 50
#define DD 64

// Shared memory partition (floats):
//  w1s 8192 | a1s 8192 | w2s 4096 | a2s 4096 | a3s 64 | b1s 64 | b2s 64
//  ab1s 64 | ab2s 64 | ub 64 | xb 16*132 | tb 16*68 | osto 50*64
//  logits 64 | att 64 | red 256
// total = 31744 floats = 126976 bytes

__global__ __launch_bounds__(256, 1)
void uv_agg_kernel(const int* __restrict__ nodes,
                   const int* __restrict__ hist_uv,
                   const int* __restrict__ hist_r,
                   const float* __restrict__ v2e,
                   const float* __restrict__ u2e,
                   const float* __restrict__ r2e,
                   const float* __restrict__ w1,
                   const float* __restrict__ b1,
                   const float* __restrict__ w2,
                   const float* __restrict__ b2,
                   const float* __restrict__ a1,
                   const float* __restrict__ ab1,
                   const float* __restrict__ a2,
                   const float* __restrict__ ab2,
                   const float* __restrict__ a3,
                   const float* __restrict__ ab3,
                   float* __restrict__ out)
{
    extern __shared__ __align__(16) float sm[];
    float* w1s  = sm;             // 8192
    float* a1s  = w1s + 8192;     // 8192
    float* w2s  = a1s + 8192;     // 4096
    float* a2s  = w2s + 4096;     // 4096
    float* a3s  = a2s + 4096;     // 64
    float* b1s  = a3s + 64;
    float* b2s  = b1s + 64;
    float* ab1s = b2s + 64;
    float* ab2s = ab1s + 64;
    float* ub   = ab2s + 64;      // 64
    float* xb   = ub + 64;        // 16*132 = 2112 (pad 132 kills 2-way group conflict)
    float* tb   = xb + 2112;      // 16*68 = 1088
    float* osto = tb + 1088;      // 50*64 = 3200
    float* logits = osto + 3200;  // 64
    float* att  = logits + 64;    // 64
    float* red  = att + 64;       // 256

    const int tid = threadIdx.x;

    // ---- Stage all weights/biases into shared once per block ----
    for (int i = tid; i < 2048; i += 256) ((float4*)w1s)[i] = ((const float4*)w1)[i];
    for (int i = tid; i < 2048; i += 256) ((float4*)a1s)[i] = ((const float4*)a1)[i];
    for (int i = tid; i < 1024; i += 256) ((float4*)w2s)[i] = ((const float4*)w2)[i];
    for (int i = tid; i < 1024; i += 256) ((float4*)a2s)[i] = ((const float4*)a2)[i];
    if (tid < 64) {
        a3s[tid]  = a3[tid];
        b1s[tid]  = b1[tid];
        b2s[tid]  = b2[tid];
        ab1s[tid] = ab1[tid];
        ab2s[tid] = ab2[tid];
    }
    const float ab3v = ab3[0];
    __syncthreads();

    const int g  = tid >> 4;   // group 0..15, one neighbor row each
    const int t  = tid & 15;   // lane in group
    const int d0 = t * 4;      // 4 output dims per thread

    for (int b = blockIdx.x; b < NB; b += gridDim.x) {
        if (tid < 64) ub[tid] = u2e[(size_t)nodes[b] * DD + tid];

        for (int c = 0; c < 4; ++c) {
            const int l = c * 16 + g;
            const bool act = (l < LN);

            // ---- Phase A: gather x = [e_uv | e_r] ----
            if (act) {
                int uv = hist_uv[b * LN + l];
                int r  = hist_r[b * LN + l];
                int rr = (r > 0) ? (r - 1) : ((r < 0) ? (r + 1) : 0);
                float4 ev = ((const float4*)(v2e + (size_t)uv * DD))[t];
                float4 er = ((const float4*)(r2e + (size_t)rr * DD))[t];
                *(float4*)&xb[g * 132 + d0]      = ev;
                *(float4*)&xb[g * 132 + 64 + d0] = er;
            }
            __syncthreads();

            // ---- Phase B: x1 = relu(x @ w1 + b1) ----
            if (act) {
                float acc0 = b1s[d0], acc1 = b1s[d0 + 1], acc2 = b1s[d0 + 2], acc3 = b1s[d0 + 3];
                const float* xp = &xb[g * 132];
                #pragma unroll 8
                for (int e = 0; e < 128; ++e) {
                    float xv = xp[e];
                    float4 w = *(const float4*)&w1s[e * 64 + d0];
                    acc0 += xv * w.x; acc1 += xv * w.y; acc2 += xv * w.z; acc3 += xv * w.w;
                }
                float4 o;
                o.x = fmaxf(acc0, 0.f); o.y = fmaxf(acc1, 0.f);
                o.z = fmaxf(acc2, 0.f); o.w = fmaxf(acc3, 0.f);
                *(float4*)&tb[g * 68 + d0] = o;
            }
            __syncthreads();

            // ---- Phase C: o = relu(x1 @ w2 + b2); build h = [o | u] ----
            if (act) {
                float acc0 = b2s[d0], acc1 = b2s[d0 + 1], acc2 = b2s[d0 + 2], acc3 = b2s[d0 + 3];
                const float* xp = &tb[g * 68];
                #pragma unroll 8
                for (int e = 0; e < 64; ++e) {
                    float xv = xp[e];
                    float4 w = *(const float4*)&w2s[e * 64 + d0];
                    acc0 += xv * w.x; acc1 += xv * w.y; acc2 += xv * w.z; acc3 += xv * w.w;
                }
                float4 o;
                o.x = fmaxf(acc0, 0.f); o.y = fmaxf(acc1, 0.f);
                o.z = fmaxf(acc2, 0.f); o.w = fmaxf(acc3, 0.f);
                *(float4*)&osto[l * 64 + d0]     = o;
                *(float4*)&xb[g * 132 + d0]      = o;
                *(float4*)&xb[g * 132 + 64 + d0] = *(const float4*)&ub[d0];
            }
            __syncthreads();

            // ---- Phase D: h1 = relu(h @ a1 + ab1) ----
            if (act) {
                float acc0 = ab1s[d0], acc1 = ab1s[d0 + 1], acc2 = ab1s[d0 + 2], acc3 = ab1s[d0 + 3];
                const float* xp = &xb[g * 132];
                #pragma unroll 8
                for (int e = 0; e < 128; ++e) {
                    float xv = xp[e];
                    float4 w = *(const float4*)&a1s[e * 64 + d0];
                    acc0 += xv * w.x; acc1 += xv * w.y; acc2 += xv * w.z; acc3 += xv * w.w;
                }
                float4 o;
                o.x = fmaxf(acc0, 0.f); o.y = fmaxf(acc1, 0.f);
                o.z = fmaxf(acc2, 0.f); o.w = fmaxf(acc3, 0.f);
                *(float4*)&tb[g * 68 + d0] = o;
            }
            __syncthreads();

            // ---- Phase E: h2 = relu(h1 @ a2 + ab2); logit = h2 . a3 ----
            if (act) {
                float acc0 = ab2s[d0], acc1 = ab2s[d0 + 1], acc2 = ab2s[d0 + 2], acc3 = ab2s[d0 + 3];
                const float* xp = &tb[g * 68];
                #pragma unroll 8
                for (int e = 0; e < 64; ++e) {
                    float xv = xp[e];
                    float4 w = *(const float4*)&a2s[e * 64 + d0];
                    acc0 += xv * w.x; acc1 += xv * w.y; acc2 += xv * w.z; acc3 += xv * w.w;
                }
                float p = fmaxf(acc0, 0.f) * a3s[d0]
                        + fmaxf(acc1, 0.f) * a3s[d0 + 1]
                        + fmaxf(acc2, 0.f) * a3s[d0 + 2]
                        + fmaxf(acc3, 0.f) * a3s[d0 + 3];
                // reduce across the 16 lanes of this group (one warp half)
                unsigned mask = 0xFFFFu << (tid & 16);
                p += __shfl_xor_sync(mask, p, 1);
                p += __shfl_xor_sync(mask, p, 2);
                p += __shfl_xor_sync(mask, p, 4);
                p += __shfl_xor_sync(mask, p, 8);
                if (t == 0) logits[l] = p + ab3v;
            }
            __syncthreads();
        }

        // ---- Softmax over logits[0..49] (warp 0) ----
        if (tid < 32) {
            float v1 = logits[tid];
            float v2 = (tid + 32 < LN) ? logits[tid + 32] : -1e30f;
            float m = fmaxf(v1, v2);
            #pragma unroll
            for (int off = 16; off; off >>= 1)
                m = fmaxf(m, __shfl_xor_sync(0xffffffffu, m, off));
            float e1 = expf(v1 - m);
            float e2 = (tid + 32 < LN) ? expf(v2 - m) : 0.f;
            float s = e1 + e2;
            #pragma unroll
            for (int off = 16; off; off >>= 1)
                s += __shfl_xor_sync(0xffffffffu, s, off);
            float inv = 1.f / s;
            att[tid] = e1 * inv;
            if (tid + 32 < LN) att[tid + 32] = e2 * inv;
        }
        __syncthreads();

        // ---- Aggregation: out[b,d] = sum_l o[l,d] * att[l] ----
        {
            int d = tid & 63;
            int q = tid >> 6;
            float acc = 0.f;
            for (int l = q; l < LN; l += 4) acc += osto[l * 64 + d] * att[l];
            red[tid] = acc;
        }
        __syncthreads();
        if (tid < 64)
            out[(size_t)b * DD + tid] = red[tid] + red[64 + tid] + red[128 + tid] + red[192 + tid];
        __syncthreads();
    }
}

extern "C" void kernel_launch(void* const* d_in, const int* in_sizes, int n_in,
                              void* d_out, int out_size)
{
    const int*   nodes = (const int*)d_in[0];
    const int*   huv   = (const int*)d_in[1];
    const int*   hr    = (const int*)d_in[2];
    const float* v2e   = (const float*)d_in[3];
    const float* u2e   = (const float*)d_in[4];
    const float* r2e   = (const float*)d_in[5];
    const float* w1    = (const float*)d_in[6];
    const float* b1    = (const float*)d_in[7];
    const float* w2    = (const float*)d_in[8];
    const float* b2    = (const float*)d_in[9];
    const float* a1    = (const float*)d_in[10];
    const float* ab1   = (const float*)d_in[11];
    const float* a2    = (const float*)d_in[12];
    const float* ab2   = (const float*)d_in[13];
    const float* a3    = (const float*)d_in[14];
    const float* ab3   = (const float*)d_in[15];
    float* out = (float*)d_out;

    const int smem_bytes = 31744 * 4;  // 126976
    cudaFuncSetAttribute(uv_agg_kernel,
                         cudaFuncAttributeMaxDynamicSharedMemorySize, smem_bytes);

    uv_agg_kernel<<<148, 256, smem_bytes>>>(nodes, huv, hr, v2e, u2e, r2e,
                                            w1, b1, w2, b2,
                                            a1, ab1, a2, ab2, a3, ab3, out);
}

// round 4
// speedup vs baseline: 2.3481x; 2.3481x over previous
#include <cuda_runtime.h>

#define NB 16384
#define LN 50
#define DD 64

// smem floats:
// w1s 8192 | a1s 8192 | w2s 4096 | a2s 4096 | b1s/b2s/ab1s/ab2s/a3s 5*64
// ub 64 | xb 64*132=8448 | tb 64*68=4352 | osto 50*64=3200
// logits 64 | att 64 | red 256   => total 41344 floats = 165376 B

// 4-row x 4-col register tile GEMM step over K, activations+weights in smem.
// XS4 = activation row stride in float4 units.
template<int K, int XS4>
__device__ __forceinline__ void mm_tile(const float* __restrict__ xp,
                                        const float* __restrict__ ws, int d0,
                                        float4& c0, float4& c1, float4& c2, float4& c3)
{
    const float4* x4 = (const float4*)xp;
    #pragma unroll 4
    for (int e4 = 0; e4 < K / 4; ++e4) {
        float xa0[4], xa1[4], xa2[4], xa3[4];
        *(float4*)xa0 = x4[e4];
        *(float4*)xa1 = x4[XS4 + e4];
        *(float4*)xa2 = x4[2 * XS4 + e4];
        *(float4*)xa3 = x4[3 * XS4 + e4];
        const float* wp = ws + (e4 * 4) * 64 + d0;
        #pragma unroll
        for (int j = 0; j < 4; ++j) {
            float4 w = *(const float4*)(wp + j * 64);
            c0.x += xa0[j] * w.x; c0.y += xa0[j] * w.y; c0.z += xa0[j] * w.z; c0.w += xa0[j] * w.w;
            c1.x += xa1[j] * w.x; c1.y += xa1[j] * w.y; c1.z += xa1[j] * w.z; c1.w += xa1[j] * w.w;
            c2.x += xa2[j] * w.x; c2.y += xa2[j] * w.y; c2.z += xa2[j] * w.z; c2.w += xa2[j] * w.w;
            c3.x += xa3[j] * w.x; c3.y += xa3[j] * w.y; c3.z += xa3[j] * w.z; c3.w += xa3[j] * w.w;
        }
    }
}

__device__ __forceinline__ float4 relu4(float4 c) {
    return make_float4(fmaxf(c.x, 0.f), fmaxf(c.y, 0.f), fmaxf(c.z, 0.f), fmaxf(c.w, 0.f));
}

__global__ __launch_bounds__(256, 1)
void uv_agg_kernel(const int* __restrict__ nodes,
                   const int* __restrict__ hist_uv,
                   const int* __restrict__ hist_r,
                   const float* __restrict__ v2e,
                   const float* __restrict__ u2e,
                   const float* __restrict__ r2e,
                   const float* __restrict__ w1,
                   const float* __restrict__ b1,
                   const float* __restrict__ w2,
                   const float* __restrict__ b2,
                   const float* __restrict__ a1,
                   const float* __restrict__ ab1,
                   const float* __restrict__ a2,
                   const float* __restrict__ ab2,
                   const float* __restrict__ a3,
                   const float* __restrict__ ab3,
                   float* __restrict__ out)
{
    extern __shared__ __align__(16) float sm[];
    float* w1s  = sm;             // 8192
    float* a1s  = w1s + 8192;     // 8192
    float* w2s  = a1s + 8192;     // 4096
    float* a2s  = w2s + 4096;     // 4096
    float* b1s  = a2s + 4096;     // 64
    float* b2s  = b1s + 64;
    float* ab1s = b2s + 64;
    float* ab2s = ab1s + 64;
    float* a3s  = ab2s + 64;
    float* ub   = a3s + 64;       // 64
    float* xb   = ub + 64;        // 64*132 = 8448
    float* tb   = xb + 8448;      // 64*68  = 4352
    float* osto = tb + 4352;      // 50*64  = 3200
    float* logits = osto + 3200;  // 64
    float* att  = logits + 64;    // 64
    float* red  = att + 64;       // 256

    const int tid = threadIdx.x;

    // ---- stage weights once ----
    for (int i = tid; i < 2048; i += 256) ((float4*)w1s)[i] = ((const float4*)w1)[i];
    for (int i = tid; i < 2048; i += 256) ((float4*)a1s)[i] = ((const float4*)a1)[i];
    for (int i = tid; i < 1024; i += 256) ((float4*)w2s)[i] = ((const float4*)w2)[i];
    for (int i = tid; i < 1024; i += 256) ((float4*)a2s)[i] = ((const float4*)a2)[i];
    if (tid < 64) {
        b1s[tid]  = b1[tid];
        b2s[tid]  = b2[tid];
        ab1s[tid] = ab1[tid];
        ab2s[tid] = ab2[tid];
        a3s[tid]  = a3[tid];
    }
    const float ab3v = ab3[0];
    __syncthreads();

    const int g  = tid >> 4;     // group 0..15
    const int t  = tid & 15;     // lane in group
    const int d0 = t * 4;        // 4 output dims
    const int r0 = g * 4;        // 4 rows per group (groups 0..12 active, 52 rows)
    const bool act = (g <= 12);

    for (int b = blockIdx.x; b < NB; b += gridDim.x) {
        if (tid < 64) ub[tid] = u2e[(size_t)nodes[b] * DD + tid];

        // ---- Phase A: gather x = [e_uv | e_r], row-major [row][132] ----
        if (act) {
            #pragma unroll
            for (int j = 0; j < 4; ++j) {
                int r = r0 + j;
                int l = (r < LN) ? r : (LN - 1);   // clamp padded rows
                int uv = hist_uv[b * LN + l];
                int rr = hist_r[b * LN + l];
                rr = (rr > 0) ? (rr - 1) : ((rr < 0) ? (rr + 1) : 0);
                float4 ev = ((const float4*)(v2e + (size_t)uv * DD))[t];
                float4 er = ((const float4*)(r2e + (size_t)rr * DD))[t];
                *(float4*)&xb[r * 132 + d0]      = ev;
                *(float4*)&xb[r * 132 + 64 + d0] = er;
            }
        }
        __syncthreads();

        // ---- Phase B: x1 = relu(x @ w1 + b1), K=128 ----
        if (act) {
            float4 bb = *(const float4*)&b1s[d0];
            float4 c0 = bb, c1 = bb, c2 = bb, c3 = bb;
            mm_tile<128, 33>(&xb[r0 * 132], w1s, d0, c0, c1, c2, c3);
            *(float4*)&tb[(r0 + 0) * 68 + d0] = relu4(c0);
            *(float4*)&tb[(r0 + 1) * 68 + d0] = relu4(c1);
            *(float4*)&tb[(r0 + 2) * 68 + d0] = relu4(c2);
            *(float4*)&tb[(r0 + 3) * 68 + d0] = relu4(c3);
        }
        __syncthreads();

        // ---- Phase C: o = relu(x1 @ w2 + b2), K=64; build h = [o | u] ----
        if (act) {
            float4 bb = *(const float4*)&b2s[d0];
            float4 c0 = bb, c1 = bb, c2 = bb, c3 = bb;
            mm_tile<64, 17>(&tb[r0 * 68], w2s, d0, c0, c1, c2, c3);
            float4 ubv = *(const float4*)&ub[d0];
            float4 oo[4] = {relu4(c0), relu4(c1), relu4(c2), relu4(c3)};
            #pragma unroll
            for (int j = 0; j < 4; ++j) {
                int r = r0 + j;
                if (r < LN) *(float4*)&osto[r * 64 + d0] = oo[j];
                *(float4*)&xb[r * 132 + d0]      = oo[j];
                *(float4*)&xb[r * 132 + 64 + d0] = ubv;
            }
        }
        __syncthreads();

        // ---- Phase D: h1 = relu(h @ a1 + ab1), K=128 ----
        if (act) {
            float4 bb = *(const float4*)&ab1s[d0];
            float4 c0 = bb, c1 = bb, c2 = bb, c3 = bb;
            mm_tile<128, 33>(&xb[r0 * 132], a1s, d0, c0, c1, c2, c3);
            *(float4*)&tb[(r0 + 0) * 68 + d0] = relu4(c0);
            *(float4*)&tb[(r0 + 1) * 68 + d0] = relu4(c1);
            *(float4*)&tb[(r0 + 2) * 68 + d0] = relu4(c2);
            *(float4*)&tb[(r0 + 3) * 68 + d0] = relu4(c3);
        }
        __syncthreads();

        // ---- Phase E: h2 = relu(h1 @ a2 + ab2), K=64; logit = h2 . a3 ----
        if (act) {
            float4 bb = *(const float4*)&ab2s[d0];
            float4 c0 = bb, c1 = bb, c2 = bb, c3 = bb;
            mm_tile<64, 17>(&tb[r0 * 68], a2s, d0, c0, c1, c2, c3);
            float4 a3v = *(const float4*)&a3s[d0];
            float p0 = fmaxf(c0.x,0.f)*a3v.x + fmaxf(c0.y,0.f)*a3v.y + fmaxf(c0.z,0.f)*a3v.z + fmaxf(c0.w,0.f)*a3v.w;
            float p1 = fmaxf(c1.x,0.f)*a3v.x + fmaxf(c1.y,0.f)*a3v.y + fmaxf(c1.z,0.f)*a3v.z + fmaxf(c1.w,0.f)*a3v.w;
            float p2 = fmaxf(c2.x,0.f)*a3v.x + fmaxf(c2.y,0.f)*a3v.y + fmaxf(c2.z,0.f)*a3v.z + fmaxf(c2.w,0.f)*a3v.w;
            float p3 = fmaxf(c3.x,0.f)*a3v.x + fmaxf(c3.y,0.f)*a3v.y + fmaxf(c3.z,0.f)*a3v.z + fmaxf(c3.w,0.f)*a3v.w;
            unsigned mask = 0xFFFFu << (tid & 16);
            #pragma unroll
            for (int off = 1; off < 16; off <<= 1) {
                p0 += __shfl_xor_sync(mask, p0, off);
                p1 += __shfl_xor_sync(mask, p1, off);
                p2 += __shfl_xor_sync(mask, p2, off);
                p3 += __shfl_xor_sync(mask, p3, off);
            }
            if (t == 0) {
                if (r0 + 0 < LN) logits[r0 + 0] = p0 + ab3v;
                if (r0 + 1 < LN) logits[r0 + 1] = p1 + ab3v;
                if (r0 + 2 < LN) logits[r0 + 2] = p2 + ab3v;
                if (r0 + 3 < LN) logits[r0 + 3] = p3 + ab3v;
            }
        }
        __syncthreads();

        // ---- softmax over 50 (warp 0) ----
        if (tid < 32) {
            float v1 = logits[tid];
            float v2 = (tid + 32 < LN) ? logits[tid + 32] : -1e30f;
            float m = fmaxf(v1, v2);
            #pragma unroll
            for (int off = 16; off; off >>= 1)
                m = fmaxf(m, __shfl_xor_sync(0xffffffffu, m, off));
            float e1 = expf(v1 - m);
            float e2 = (tid + 32 < LN) ? expf(v2 - m) : 0.f;
            float s = e1 + e2;
            #pragma unroll
            for (int off = 16; off; off >>= 1)
                s += __shfl_xor_sync(0xffffffffu, s, off);
            float inv = 1.f / s;
            att[tid] = e1 * inv;
            if (tid + 32 < LN) att[tid + 32] = e2 * inv;
        }
        __syncthreads();

        // ---- aggregation ----
        {
            int d = tid & 63;
            int q = tid >> 6;
            float acc = 0.f;
            for (int l = q; l < LN; l += 4) acc += osto[l * 64 + d] * att[l];
            red[tid] = acc;
        }
        __syncthreads();
        if (tid < 64)
            out[(size_t)b * DD + tid] = red[tid] + red[64 + tid] + red[128 + tid] + red[192 + tid];
        __syncthreads();
    }
}

extern "C" void kernel_launch(void* const* d_in, const int* in_sizes, int n_in,
                              void* d_out, int out_size)
{
    const int*   nodes = (const int*)d_in[0];
    const int*   huv   = (const int*)d_in[1];
    const int*   hr    = (const int*)d_in[2];
    const float* v2e   = (const float*)d_in[3];
    const float* u2e   = (const float*)d_in[4];
    const float* r2e   = (const float*)d_in[5];
    const float* w1    = (const float*)d_in[6];
    const float* b1    = (const float*)d_in[7];
    const float* w2    = (const float*)d_in[8];
    const float* b2    = (const float*)d_in[9];
    const float* a1    = (const float*)d_in[10];
    const float* ab1   = (const float*)d_in[11];
    const float* a2    = (const float*)d_in[12];
    const float* ab2   = (const float*)d_in[13];
    const float* a3    = (const float*)d_in[14];
    const float* ab3   = (const float*)d_in[15];
    float* out = (float*)d_out;

    const int smem_bytes = 41344 * 4;  // 165376
    cudaFuncSetAttribute(uv_agg_kernel,
                         cudaFuncAttributeMaxDynamicSharedMemorySize, smem_bytes);

    uv_agg_kernel<<<148, 256, smem_bytes>>>(nodes, huv, hr, v2e, u2e, r2e,
                                            w1, b1, w2, b2,
                                            a1, ab1, a2, ab2, a3, ab3, out);
}

// round 7
// speedup vs baseline: 2.4356x; 1.0373x over previous
#include <cuda_runtime.h>

#define NB 16384
#define LN 50
#define DD 64
#define RPB 52              // padded rows per batch element
#define ROWS 104            // 2 b per block
#define NGRP 13             // groups of 16 threads, 8 rows each

typedef unsigned long long ull;

static __device__ __forceinline__ void ffma2(ull& d, ull a, ull b) {
    asm("fma.rn.f32x2 %0, %1, %2, %0;" : "+l"(d) : "l"(a), "l"(b));
}
static __device__ __forceinline__ float2 upk(ull v) {
    float2 f; asm("mov.b64 {%0,%1}, %2;" : "=f"(f.x), "=f"(f.y) : "l"(v)); return f;
}
static __device__ __forceinline__ ull pk(float x, float y) {
    ull v; asm("mov.b64 %0, {%1,%2};" : "=l"(v) : "f"(x), "f"(y)); return v;
}

// 8-row x 4-col FFMA2 GEMM over K4*4 K-elements.
// xr[r]: pointer to row r's activations (K-contiguous, 16B aligned).
// ws: pair-interleaved weights [e2][2d+half], row stride 128 floats.
template<int K4>
static __device__ __forceinline__ void gemm_acc(ull (&acc)[8][4],
                                                const float* const (&xr)[8],
                                                const float* ws, int t, int e2base)
{
    #pragma unroll 2
    for (int e4 = 0; e4 < K4; ++e4) {
        const float* wb = ws + (e2base + 2 * e4) * 128 + 4 * t;
        ulonglong2 wA0 = *(const ulonglong2*)(wb);
        ulonglong2 wB0 = *(const ulonglong2*)(wb + 64);
        ulonglong2 wA1 = *(const ulonglong2*)(wb + 128);
        ulonglong2 wB1 = *(const ulonglong2*)(wb + 192);
        #pragma unroll
        for (int r = 0; r < 8; ++r) {
            ulonglong2 xv = *(const ulonglong2*)(xr[r] + 4 * e4);
            ffma2(acc[r][0], xv.x, wA0.x);
            ffma2(acc[r][1], xv.x, wA0.y);
            ffma2(acc[r][2], xv.x, wB0.x);
            ffma2(acc[r][3], xv.x, wB0.y);
            ffma2(acc[r][0], xv.y, wA1.x);
            ffma2(acc[r][1], xv.y, wA1.y);
            ffma2(acc[r][2], xv.y, wB1.x);
            ffma2(acc[r][3], xv.y, wB1.y);
        }
    }
}

__global__ __launch_bounds__(256, 1)
void uv_agg_kernel(const int* __restrict__ nodes,
                   const int* __restrict__ hist_uv,
                   const int* __restrict__ hist_r,
                   const float* __restrict__ v2e,
                   const float* __restrict__ u2e,
                   const float* __restrict__ r2e,
                   const float* __restrict__ w1,
                   const float* __restrict__ b1,
                   const float* __restrict__ w2,
                   const float* __restrict__ b2,
                   const float* __restrict__ a1,
                   const float* __restrict__ ab1,
                   const float* __restrict__ a2,
                   const float* __restrict__ ab2,
                   const float* __restrict__ a3,
                   const float* __restrict__ ab3,
                   float* __restrict__ out)
{
    extern __shared__ __align__(16) float sm[];
    float* wp1s = sm;              // 8192  pair-interleaved w1
    float* ap1s = wp1s + 8192;     // 8192  a1
    float* wp2s = ap1s + 8192;     // 4096  w2
    float* ap2s = wp2s + 4096;     // 4096  a2
    float* b1s  = ap2s + 4096;     // 64
    float* b2s  = b1s + 64;
    float* ab1s = b2s + 64;
    float* ab2s = ab1s + 64;
    float* a3s  = ab2s + 64;
    float* r2s  = a3s + 64;        // 5*68 = 340
    float* ubS  = r2s + 340;       // 2*68 = 136
    float* xb   = ubS + 136;       // 104*68 = 7072  (e_uv)
    float* tb   = xb + 7072;       // 104*68 = 7072
    float* ob   = tb + 7072;       // 104*68 = 7072
    int*   rrs  = (int*)(ob + 7072);   // 104
    float* logits = ob + 7072 + 104;   // 128 (64 per b)
    float* att  = logits + 128;        // 128
    float* red  = att + 128;           // 256
    // total 47204 floats

    const int tid = threadIdx.x;

    // ---- stage weights (pair-interleaved over K) ----
    for (int i = tid; i < 8192; i += 256) {
        int e2 = i >> 7, rem = i & 127, d = rem >> 1, h = rem & 1;
        wp1s[i] = w1[(2 * e2 + h) * 64 + d];
        ap1s[i] = a1[(2 * e2 + h) * 64 + d];
    }
    for (int i = tid; i < 4096; i += 256) {
        int e2 = i >> 7, rem = i & 127, d = rem >> 1, h = rem & 1;
        wp2s[i] = w2[(2 * e2 + h) * 64 + d];
        ap2s[i] = a2[(2 * e2 + h) * 64 + d];
    }
    if (tid < 64) {
        b1s[tid]  = b1[tid];
        b2s[tid]  = b2[tid];
        ab1s[tid] = ab1[tid];
        ab2s[tid] = ab2[tid];
        a3s[tid]  = a3[tid];
    }
    for (int i = tid; i < 5 * 64; i += 256)
        r2s[(i >> 6) * 68 + (i & 63)] = r2e[i];
    const float ab3v = ab3[0];
    __syncthreads();

    const int g  = tid >> 4;       // group 0..15 (0..12 active)
    const int t  = tid & 15;
    const int r0 = g * 8;
    const bool act = (g < NGRP);
    const unsigned smask = 0xFFFFu << (tid & 16);

    for (int pr = blockIdx.x; pr < NB / 2; pr += gridDim.x) {
        const int b0 = pr * 2;

        // ---- Phase A: gather e_uv rows + rr; load u rows ----
        if (tid < 128) {
            int q = tid >> 6;
            ubS[q * 68 + (tid & 63)] = u2e[(size_t)nodes[b0 + q] * DD + (tid & 63)];
        }
        if (act) {
            #pragma unroll
            for (int j = 0; j < 8; ++j) {
                int row = r0 + j;
                int bs = (row >= RPB);
                int l = row - RPB * bs;
                if (l > LN - 1) l = LN - 1;
                int uv = hist_uv[(b0 + bs) * LN + l];
                int rv = hist_r[(b0 + bs) * LN + l];
                int rr = (rv > 0) ? (rv - 1) : ((rv < 0) ? (rv + 1) : 0);
                if (t == 0) rrs[row] = rr;
                float4 ev = ((const float4*)(v2e + (size_t)uv * DD))[t];
                *(float4*)&xb[row * 68 + 4 * t] = ev;
            }
        }
        __syncthreads();

        ull acc[8][4];
        const float* xr[8];
        const int cA = 2 * t, cB = 2 * t + 32;

        // ---- Phase B: x1 = relu([e_uv|e_r] @ w1 + b1) -> tb ----
        if (act) {
            #pragma unroll
            for (int r = 0; r < 8; ++r) {
                acc[r][0] = pk(b1s[cA], 0.f);
                acc[r][1] = pk(b1s[cA + 1], 0.f);
                acc[r][2] = pk(b1s[cB], 0.f);
                acc[r][3] = pk(b1s[cB + 1], 0.f);
            }
            #pragma unroll
            for (int r = 0; r < 8; ++r) xr[r] = &xb[(r0 + r) * 68];
            gemm_acc<16>(acc, xr, wp1s, t, 0);
            #pragma unroll
            for (int r = 0; r < 8; ++r) xr[r] = &r2s[rrs[r0 + r] * 68];
            gemm_acc<16>(acc, xr, wp1s, t, 32);
            #pragma unroll
            for (int r = 0; r < 8; ++r) {
                float2 u0 = upk(acc[r][0]), u1 = upk(acc[r][1]);
                float2 u2 = upk(acc[r][2]), u3 = upk(acc[r][3]);
                float2 vA = {fmaxf(u0.x + u0.y, 0.f), fmaxf(u1.x + u1.y, 0.f)};
                float2 vB = {fmaxf(u2.x + u2.y, 0.f), fmaxf(u3.x + u3.y, 0.f)};
                *(float2*)&tb[(r0 + r) * 68 + cA] = vA;
                *(float2*)&tb[(r0 + r) * 68 + cB] = vB;
            }
        }
        __syncthreads();

        // ---- Phase C: o = relu(x1 @ w2 + b2) -> ob ----
        if (act) {
            #pragma unroll
            for (int r = 0; r < 8; ++r) {
                acc[r][0] = pk(b2s[cA], 0.f);
                acc[r][1] = pk(b2s[cA + 1], 0.f);
                acc[r][2] = pk(b2s[cB], 0.f);
                acc[r][3] = pk(b2s[cB + 1], 0.f);
            }
            #pragma unroll
            for (int r = 0; r < 8; ++r) xr[r] = &tb[(r0 + r) * 68];
            gemm_acc<16>(acc, xr, wp2s, t, 0);
            #pragma unroll
            for (int r = 0; r < 8; ++r) {
                float2 u0 = upk(acc[r][0]), u1 = upk(acc[r][1]);
                float2 u2 = upk(acc[r][2]), u3 = upk(acc[r][3]);
                float2 vA = {fmaxf(u0.x + u0.y, 0.f), fmaxf(u1.x + u1.y, 0.f)};
                float2 vB = {fmaxf(u2.x + u2.y, 0.f), fmaxf(u3.x + u3.y, 0.f)};
                *(float2*)&ob[(r0 + r) * 68 + cA] = vA;
                *(float2*)&ob[(r0 + r) * 68 + cB] = vB;
            }
        }
        __syncthreads();

        // ---- Phase D: h1 = relu([o|u] @ a1 + ab1) -> tb ----
        if (act) {
            #pragma unroll
            for (int r = 0; r < 8; ++r) {
                acc[r][0] = pk(ab1s[cA], 0.f);
                acc[r][1] = pk(ab1s[cA + 1], 0.f);
                acc[r][2] = pk(ab1s[cB], 0.f);
                acc[r][3] = pk(ab1s[cB + 1], 0.f);
            }
            #pragma unroll
            for (int r = 0; r < 8; ++r) xr[r] = &ob[(r0 + r) * 68];
            gemm_acc<16>(acc, xr, ap1s, t, 0);
            #pragma unroll
            for (int r = 0; r < 8; ++r) xr[r] = &ubS[((r0 + r) >= RPB) ? 68 : 0];
            gemm_acc<16>(acc, xr, ap1s, t, 32);
            #pragma unroll
            for (int r = 0; r < 8; ++r) {
                float2 u0 = upk(acc[r][0]), u1 = upk(acc[r][1]);
                float2 u2 = upk(acc[r][2]), u3 = upk(acc[r][3]);
                float2 vA = {fmaxf(u0.x + u0.y, 0.f), fmaxf(u1.x + u1.y, 0.f)};
                float2 vB = {fmaxf(u2.x + u2.y, 0.f), fmaxf(u3.x + u3.y, 0.f)};
                *(float2*)&tb[(r0 + r) * 68 + cA] = vA;
                *(float2*)&tb[(r0 + r) * 68 + cB] = vB;
            }
        }
        __syncthreads();

        // ---- Phase E: h2 = relu(h1 @ a2 + ab2); logit = h2 . a3 ----
        if (act) {
            #pragma unroll
            for (int r = 0; r < 8; ++r) {
                acc[r][0] = pk(ab2s[cA], 0.f);
                acc[r][1] = pk(ab2s[cA + 1], 0.f);
                acc[r][2] = pk(ab2s[cB], 0.f);
                acc[r][3] = pk(ab2s[cB + 1], 0.f);
            }
            #pragma unroll
            for (int r = 0; r < 8; ++r) xr[r] = &tb[(r0 + r) * 68];
            gemm_acc<16>(acc, xr, ap2s, t, 0);
            float a30 = a3s[cA], a31 = a3s[cA + 1], a32 = a3s[cB], a33 = a3s[cB + 1];
            #pragma unroll
            for (int r = 0; r < 8; ++r) {
                float2 u0 = upk(acc[r][0]), u1 = upk(acc[r][1]);
                float2 u2 = upk(acc[r][2]), u3 = upk(acc[r][3]);
                float p = fmaxf(u0.x + u0.y, 0.f) * a30
                        + fmaxf(u1.x + u1.y, 0.f) * a31
                        + fmaxf(u2.x + u2.y, 0.f) * a32
                        + fmaxf(u3.x + u3.y, 0.f) * a33;
                p += __shfl_xor_sync(smask, p, 1);
                p += __shfl_xor_sync(smask, p, 2);
                p += __shfl_xor_sync(smask, p, 4);
                p += __shfl_xor_sync(smask, p, 8);
                if (t == 0) {
                    int row = r0 + r;
                    int bs = (row >= RPB);
                    int l = row - RPB * bs;
                    if (l < LN) logits[bs * 64 + l] = p + ab3v;
                }
            }
        }
        __syncthreads();

        // ---- softmax: warp 0 -> b0, warp 1 -> b1 ----
        if (tid < 64) {
            int w = tid >> 5, lane = tid & 31;
            const float* lg = &logits[w * 64];
            float v1 = lg[lane];
            float v2 = (lane + 32 < LN) ? lg[lane + 32] : -1e30f;
            float m = fmaxf(v1, v2);
            #pragma unroll
            for (int off = 16; off; off >>= 1)
                m = fmaxf(m, __shfl_xor_sync(0xffffffffu, m, off));
            float e1 = expf(v1 - m);
            float e2 = (lane + 32 < LN) ? expf(v2 - m) : 0.f;
            float s = e1 + e2;
            #pragma unroll
            for (int off = 16; off; off >>= 1)
                s += __shfl_xor_sync(0xffffffffu, s, off);
            float inv = 1.f / s;
            att[w * 64 + lane] = e1 * inv;
            if (lane + 32 < LN) att[w * 64 + lane + 32] = e2 * inv;
        }
        __syncthreads();

        // ---- aggregation: out[b,d] = sum_l o[l,d]*att[l] ----
        {
            int bs = tid >> 7;
            int k = tid & 127;
            int d = k & 63, q = k >> 6;
            const float* ap = &att[bs * 64];
            const float* op = &ob[RPB * bs * 68];
            float acc2 = 0.f;
            for (int l = q; l < LN; l += 2) acc2 += op[l * 68 + d] * ap[l];
            red[tid] = acc2;
        }
        __syncthreads();
        if (tid < 128) {
            int bs = tid >> 6, d = tid & 63;
            out[(size_t)(b0 + bs) * DD + d] = red[bs * 128 + d] + red[bs * 128 + 64 + d];
        }
        __syncthreads();
    }
}

extern "C" void kernel_launch(void* const* d_in, const int* in_sizes, int n_in,
                              void* d_out, int out_size)
{
    const int*   nodes = (const int*)d_in[0];
    const int*   huv   = (const int*)d_in[1];
    const int*   hr    = (const int*)d_in[2];
    const float* v2e   = (const float*)d_in[3];
    const float* u2e   = (const float*)d_in[4];
    const float* r2e   = (const float*)d_in[5];
    const float* w1    = (const float*)d_in[6];
    const float* b1    = (const float*)d_in[7];
    const float* w2    = (const float*)d_in[8];
    const float* b2    = (const float*)d_in[9];
    const float* a1    = (const float*)d_in[10];
    const float* ab1   = (const float*)d_in[11];
    const float* a2    = (const float*)d_in[12];
    const float* ab2   = (const float*)d_in[13];
    const float* a3    = (const float*)d_in[14];
    const float* ab3   = (const float*)d_in[15];
    float* out = (float*)d_out;

    const int smem_bytes = 47204 * 4;  // 188816
    cudaFuncSetAttribute(uv_agg_kernel,
                         cudaFuncAttributeMaxDynamicSharedMemorySize, smem_bytes);

    uv_agg_kernel<<<148, 256, smem_bytes>>>(nodes, huv, hr, v2e, u2e, r2e,
                                            w1, b1, w2, b2,
                                            a1, ab1, a2, ab2, a3, ab3, out);
}

// round 8
// speedup vs baseline: 2.5654x; 1.0533x over previous
#include <cuda_runtime.h>

#define NB 16384
#define LN 50
#define DD 64
#define RPB 52              // padded rows per batch element
#define BPB 4               // batch elements per block
#define ROWS 208            // BPB * RPB
#define NGRP 26             // groups of 16 threads, 8 rows each
#define NTHR 512

typedef unsigned long long ull;

static __device__ __forceinline__ void ffma2(ull& d, ull a, ull b) {
    asm("fma.rn.f32x2 %0, %1, %2, %0;" : "+l"(d) : "l"(a), "l"(b));
}
static __device__ __forceinline__ float2 upk(ull v) {
    float2 f; asm("mov.b64 {%0,%1}, %2;" : "=f"(f.x), "=f"(f.y) : "l"(v)); return f;
}
static __device__ __forceinline__ ull pk(float x, float y) {
    ull v; asm("mov.b64 %0, {%1,%2};" : "=l"(v) : "f"(x), "f"(y)); return v;
}

// 8-row x 4-col FFMA2 GEMM over K4*4 K-elements.
// xr[r]: pointer to row r's activations (K-contiguous, 16B aligned).
// ws: pair-interleaved weights [e2][2d+half], row stride 128 floats.
template<int K4>
static __device__ __forceinline__ void gemm_acc(ull (&acc)[8][4],
                                                const float* const (&xr)[8],
                                                const float* ws, int t, int e2base)
{
    #pragma unroll 2
    for (int e4 = 0; e4 < K4; ++e4) {
        const float* wb = ws + (e2base + 2 * e4) * 128 + 4 * t;
        ulonglong2 wA0 = *(const ulonglong2*)(wb);
        ulonglong2 wB0 = *(const ulonglong2*)(wb + 64);
        ulonglong2 wA1 = *(const ulonglong2*)(wb + 128);
        ulonglong2 wB1 = *(const ulonglong2*)(wb + 192);
        #pragma unroll
        for (int r = 0; r < 8; ++r) {
            ulonglong2 xv = *(const ulonglong2*)(xr[r] + 4 * e4);
            ffma2(acc[r][0], xv.x, wA0.x);
            ffma2(acc[r][1], xv.x, wA0.y);
            ffma2(acc[r][2], xv.x, wB0.x);
            ffma2(acc[r][3], xv.x, wB0.y);
            ffma2(acc[r][0], xv.y, wA1.x);
            ffma2(acc[r][1], xv.y, wA1.y);
            ffma2(acc[r][2], xv.y, wB1.x);
            ffma2(acc[r][3], xv.y, wB1.y);
        }
    }
}

__global__ __launch_bounds__(NTHR, 1)
void uv_agg_kernel(const int* __restrict__ nodes,
                   const int* __restrict__ hist_uv,
                   const int* __restrict__ hist_r,
                   const float* __restrict__ v2e,
                   const float* __restrict__ u2e,
                   const float* __restrict__ r2e,
                   const float* __restrict__ w1,
                   const float* __restrict__ b1,
                   const float* __restrict__ w2,
                   const float* __restrict__ b2,
                   const float* __restrict__ a1,
                   const float* __restrict__ ab1,
                   const float* __restrict__ a2,
                   const float* __restrict__ ab2,
                   const float* __restrict__ a3,
                   const float* __restrict__ ab3,
                   float* __restrict__ out)
{
    extern __shared__ __align__(16) float sm[];
    float* wp1s = sm;              // 8192  pair-interleaved w1
    float* ap1s = wp1s + 8192;     // 8192  a1
    float* wp2s = ap1s + 8192;     // 4096  w2
    float* ap2s = wp2s + 4096;     // 4096  a2
    float* b1s  = ap2s + 4096;     // 64
    float* b2s  = b1s + 64;
    float* ab1s = b2s + 64;
    float* ab2s = ab1s + 64;
    float* a3s  = ab2s + 64;
    float* r2s  = a3s + 64;        // 5*68 = 340
    float* ubS  = r2s + 340;       // 4*68 = 272
    float* xb   = ubS + 272;       // 208*68 = 14144 (e_uv, then o)
    float* tb   = xb + 14144;      // 208*68 = 14144
    int*   rrs  = (int*)(tb + 14144);  // 208
    float* logits = tb + 14144 + 208;  // 256 (64 per b)
    float* att  = logits + 256;        // 256
    float* red  = att + 256;           // 512
    // total = 24576+320+340+272+14144+14144+208+256+256+512 = 55028 floats

    const int tid = threadIdx.x;

    // ---- stage weights (pair-interleaved over K) ----
    for (int i = tid; i < 8192; i += NTHR) {
        int e2 = i >> 7, rem = i & 127, d = rem >> 1, h = rem & 1;
        wp1s[i] = w1[(2 * e2 + h) * 64 + d];
        ap1s[i] = a1[(2 * e2 + h) * 64 + d];
    }
    for (int i = tid; i < 4096; i += NTHR) {
        int e2 = i >> 7, rem = i & 127, d = rem >> 1, h = rem & 1;
        wp2s[i] = w2[(2 * e2 + h) * 64 + d];
        ap2s[i] = a2[(2 * e2 + h) * 64 + d];
    }
    if (tid < 64) {
        b1s[tid]  = b1[tid];
        b2s[tid]  = b2[tid];
        ab1s[tid] = ab1[tid];
        ab2s[tid] = ab2[tid];
        a3s[tid]  = a3[tid];
    }
    for (int i = tid; i < 5 * 64; i += NTHR)
        r2s[(i >> 6) * 68 + (i & 63)] = r2e[i];
    const float ab3v = ab3[0];
    __syncthreads();

    const int g  = tid >> 4;       // group 0..31 (0..25 active)
    const int t  = tid & 15;
    const int r0 = g * 8;
    const bool act = (g < NGRP);
    const unsigned smask = 0xFFFFu << (tid & 16);

    for (int pr = blockIdx.x; pr < NB / BPB; pr += gridDim.x) {
        const int b0 = pr * BPB;

        // ---- Phase A: gather e_uv rows + rr; load u rows ----
        if (tid < BPB * 64) {
            int q = tid >> 6;
            ubS[q * 68 + (tid & 63)] = u2e[(size_t)nodes[b0 + q] * DD + (tid & 63)];
        }
        if (act) {
            #pragma unroll
            for (int j = 0; j < 8; ++j) {
                int row = r0 + j;
                int bs = row / RPB;
                int l = row - RPB * bs;
                if (l > LN - 1) l = LN - 1;
                int uv = hist_uv[(b0 + bs) * LN + l];
                int rv = hist_r[(b0 + bs) * LN + l];
                int rr = (rv > 0) ? (rv - 1) : ((rv < 0) ? (rv + 1) : 0);
                if (t == 0) rrs[row] = rr;
                float4 ev = ((const float4*)(v2e + (size_t)uv * DD))[t];
                *(float4*)&xb[row * 68 + 4 * t] = ev;
            }
        }
        __syncthreads();

        ull acc[8][4];
        const float* xr[8];
        const int cA = 2 * t, cB = 2 * t + 32;

        // ---- Phase B: x1 = relu([e_uv|e_r] @ w1 + b1) -> tb ----
        if (act) {
            #pragma unroll
            for (int r = 0; r < 8; ++r) {
                acc[r][0] = pk(b1s[cA], 0.f);
                acc[r][1] = pk(b1s[cA + 1], 0.f);
                acc[r][2] = pk(b1s[cB], 0.f);
                acc[r][3] = pk(b1s[cB + 1], 0.f);
            }
            #pragma unroll
            for (int r = 0; r < 8; ++r) xr[r] = &xb[(r0 + r) * 68];
            gemm_acc<16>(acc, xr, wp1s, t, 0);
            #pragma unroll
            for (int r = 0; r < 8; ++r) xr[r] = &r2s[rrs[r0 + r] * 68];
            gemm_acc<16>(acc, xr, wp1s, t, 32);
            #pragma unroll
            for (int r = 0; r < 8; ++r) {
                float2 u0 = upk(acc[r][0]), u1 = upk(acc[r][1]);
                float2 u2 = upk(acc[r][2]), u3 = upk(acc[r][3]);
                float2 vA = {fmaxf(u0.x + u0.y, 0.f), fmaxf(u1.x + u1.y, 0.f)};
                float2 vB = {fmaxf(u2.x + u2.y, 0.f), fmaxf(u3.x + u3.y, 0.f)};
                *(float2*)&tb[(r0 + r) * 68 + cA] = vA;
                *(float2*)&tb[(r0 + r) * 68 + cB] = vB;
            }
        }
        __syncthreads();

        // ---- Phase C: o = relu(x1 @ w2 + b2) -> xb (overwrites e_uv) ----
        if (act) {
            #pragma unroll
            for (int r = 0; r < 8; ++r) {
                acc[r][0] = pk(b2s[cA], 0.f);
                acc[r][1] = pk(b2s[cA + 1], 0.f);
                acc[r][2] = pk(b2s[cB], 0.f);
                acc[r][3] = pk(b2s[cB + 1], 0.f);
            }
            #pragma unroll
            for (int r = 0; r < 8; ++r) xr[r] = &tb[(r0 + r) * 68];
            gemm_acc<16>(acc, xr, wp2s, t, 0);
            #pragma unroll
            for (int r = 0; r < 8; ++r) {
                float2 u0 = upk(acc[r][0]), u1 = upk(acc[r][1]);
                float2 u2 = upk(acc[r][2]), u3 = upk(acc[r][3]);
                float2 vA = {fmaxf(u0.x + u0.y, 0.f), fmaxf(u1.x + u1.y, 0.f)};
                float2 vB = {fmaxf(u2.x + u2.y, 0.f), fmaxf(u3.x + u3.y, 0.f)};
                *(float2*)&xb[(r0 + r) * 68 + cA] = vA;
                *(float2*)&xb[(r0 + r) * 68 + cB] = vB;
            }
        }
        __syncthreads();

        // ---- Phase D: h1 = relu([o|u] @ a1 + ab1) -> tb ----
        if (act) {
            #pragma unroll
            for (int r = 0; r < 8; ++r) {
                acc[r][0] = pk(ab1s[cA], 0.f);
                acc[r][1] = pk(ab1s[cA + 1], 0.f);
                acc[r][2] = pk(ab1s[cB], 0.f);
                acc[r][3] = pk(ab1s[cB + 1], 0.f);
            }
            #pragma unroll
            for (int r = 0; r < 8; ++r) xr[r] = &xb[(r0 + r) * 68];
            gemm_acc<16>(acc, xr, ap1s, t, 0);
            #pragma unroll
            for (int r = 0; r < 8; ++r) xr[r] = &ubS[((r0 + r) / RPB) * 68];
            gemm_acc<16>(acc, xr, ap1s, t, 32);
            #pragma unroll
            for (int r = 0; r < 8; ++r) {
                float2 u0 = upk(acc[r][0]), u1 = upk(acc[r][1]);
                float2 u2 = upk(acc[r][2]), u3 = upk(acc[r][3]);
                float2 vA = {fmaxf(u0.x + u0.y, 0.f), fmaxf(u1.x + u1.y, 0.f)};
                float2 vB = {fmaxf(u2.x + u2.y, 0.f), fmaxf(u3.x + u3.y, 0.f)};
                *(float2*)&tb[(r0 + r) * 68 + cA] = vA;
                *(float2*)&tb[(r0 + r) * 68 + cB] = vB;
            }
        }
        __syncthreads();

        // ---- Phase E: h2 = relu(h1 @ a2 + ab2); logit = h2 . a3 ----
        if (act) {
            #pragma unroll
            for (int r = 0; r < 8; ++r) {
                acc[r][0] = pk(ab2s[cA], 0.f);
                acc[r][1] = pk(ab2s[cA + 1], 0.f);
                acc[r][2] = pk(ab2s[cB], 0.f);
                acc[r][3] = pk(ab2s[cB + 1], 0.f);
            }
            #pragma unroll
            for (int r = 0; r < 8; ++r) xr[r] = &tb[(r0 + r) * 68];
            gemm_acc<16>(acc, xr, ap2s, t, 0);
            float a30 = a3s[cA], a31 = a3s[cA + 1], a32 = a3s[cB], a33 = a3s[cB + 1];
            #pragma unroll
            for (int r = 0; r < 8; ++r) {
                float2 u0 = upk(acc[r][0]), u1 = upk(acc[r][1]);
                float2 u2 = upk(acc[r][2]), u3 = upk(acc[r][3]);
                float p = fmaxf(u0.x + u0.y, 0.f) * a30
                        + fmaxf(u1.x + u1.y, 0.f) * a31
                        + fmaxf(u2.x + u2.y, 0.f) * a32
                        + fmaxf(u3.x + u3.y, 0.f) * a33;
                p += __shfl_xor_sync(smask, p, 1);
                p += __shfl_xor_sync(smask, p, 2);
                p += __shfl_xor_sync(smask, p, 4);
                p += __shfl_xor_sync(smask, p, 8);
                if (t == 0) {
                    int row = r0 + r;
                    int bs = row / RPB;
                    int l = row - RPB * bs;
                    if (l < LN) logits[bs * 64 + l] = p + ab3v;
                }
            }
        }
        __syncthreads();

        // ---- softmax: warps 0..3 -> b0..b3 ----
        if (tid < BPB * 32) {
            int w = tid >> 5, lane = tid & 31;
            const float* lg = &logits[w * 64];
            float v1 = lg[lane];
            float v2 = (lane + 32 < LN) ? lg[lane + 32] : -1e30f;
            float m = fmaxf(v1, v2);
            #pragma unroll
            for (int off = 16; off; off >>= 1)
                m = fmaxf(m, __shfl_xor_sync(0xffffffffu, m, off));
            float e1 = expf(v1 - m);
            float e2 = (lane + 32 < LN) ? expf(v2 - m) : 0.f;
            float s = e1 + e2;
            #pragma unroll
            for (int off = 16; off; off >>= 1)
                s += __shfl_xor_sync(0xffffffffu, s, off);
            float inv = 1.f / s;
            att[w * 64 + lane] = e1 * inv;
            if (lane + 32 < LN) att[w * 64 + lane + 32] = e2 * inv;
        }
        __syncthreads();

        // ---- aggregation: out[b,d] = sum_l o[l,d]*att[l]  (o lives in xb) ----
        {
            int bs = tid >> 7;              // 0..3
            int k = tid & 127;
            int d = k & 63, q = k >> 6;     // q in {0,1}
            const float* ap = &att[bs * 64];
            const float* op = &xb[RPB * bs * 68];
            float acc2 = 0.f;
            for (int l = q; l < LN; l += 2) acc2 += op[l * 68 + d] * ap[l];
            red[tid] = acc2;
        }
        __syncthreads();
        if (tid < BPB * 64) {
            int bs = tid >> 6, d = tid & 63;
            out[(size_t)(b0 + bs) * DD + d] = red[bs * 128 + d] + red[bs * 128 + 64 + d];
        }
        __syncthreads();
    }
}

extern "C" void kernel_launch(void* const* d_in, const int* in_sizes, int n_in,
                              void* d_out, int out_size)
{
    const int*   nodes = (const int*)d_in[0];
    const int*   huv   = (const int*)d_in[1];
    const int*   hr    = (const int*)d_in[2];
    const float* v2e   = (const float*)d_in[3];
    const float* u2e   = (const float*)d_in[4];
    const float* r2e   = (const float*)d_in[5];
    const float* w1    = (const float*)d_in[6];
    const float* b1    = (const float*)d_in[7];
    const float* w2    = (const float*)d_in[8];
    const float* b2    = (const float*)d_in[9];
    const float* a1    = (const float*)d_in[10];
    const float* ab1   = (const float*)d_in[11];
    const float* a2    = (const float*)d_in[12];
    const float* ab2   = (const float*)d_in[13];
    const float* a3    = (const float*)d_in[14];
    const float* ab3   = (const float*)d_in[15];
    float* out = (float*)d_out;

    const int smem_bytes = 55028 * 4;  // 220112
    cudaFuncSetAttribute(uv_agg_kernel,
                         cudaFuncAttributeMaxDynamicSharedMemorySize, smem_bytes);

    uv_agg_kernel<<<148, NTHR, smem_bytes>>>(nodes, huv, hr, v2e, u2e, r2e,
                                             w1, b1, w2, b2,
                                             a1, ab1, a2, ab2, a3, ab3, out);
}

// round 11
// speedup vs baseline: 4.3590x; 1.6991x over previous
#include <cuda_runtime.h>
#include <cstdint>

#define NB 16384
#define LN 50
#define NTILES (NB / 2)
#define NTHR 256

// smem float offsets
#define O_W1P 0
#define O_A1P 8192
#define O_W2P 16384
#define O_A2P 20480
#define O_B1  24576
#define O_B2  24640
#define O_AB1 24704
#define O_AB2 24768
#define O_A3  24832
#define O_R2S 24896
#define O_UBS 25216
#define O_BUFA 25344
#define O_BUFB 41728
#define O_LGP 49920
#define O_ATT 50176
#define O_RED 50304
#define SM_FLOATS 50560
#define SMEM_REQ (SM_FLOATS * 4)

static __device__ __forceinline__ uint32_t tf32r(float x) {
    uint32_t y; asm("cvt.rn.tf32.f32 %0, %1;" : "=r"(y) : "f"(x)); return y;
}
static __device__ __forceinline__ float tf32f(float x) {
    return __uint_as_float(tf32r(x));
}

// fragment-major index: value (row r, col k) of an M=128 x K=8*S activation
// matrix, stored so a warp's A-fragment load is one coalesced float4.
static __device__ __forceinline__ int aidx(int r, int k, int S) {
    return (((r >> 4) * S + (k >> 3)) * 32 + (((r & 7) << 2) | (k & 3))) * 4
         + ((((k & 7) >> 2) << 1) | ((r & 15) >> 3));
}

static __device__ __forceinline__ void mma8(float& c0, float& c1, float& c2, float& c3,
                                            uint4 a, uint2 b) {
    asm volatile(
        "mma.sync.aligned.m16n8k8.row.col.f32.tf32.tf32.f32 "
        "{%0,%1,%2,%3},{%4,%5,%6,%7},{%8,%9},{%0,%1,%2,%3};"
        : "+f"(c0), "+f"(c1), "+f"(c2), "+f"(c3)
        : "r"(a.x), "r"(a.y), "r"(a.z), "r"(a.w), "r"(b.x), "r"(b.y));
}

// One GEMM phase for one warp: rows [g0*16, g0*16+32), cols [nh*32, nh*32+32),
// K = 8*S. A in frag-major smem, B pair-interleaved smem -> registers.
template<int S>
static __device__ __forceinline__ void gemm_phase(const float* __restrict__ Abuf,
                                                  const float* __restrict__ Bp,
                                                  int nh, int g0, int lane,
                                                  float C[2][4][4]) {
    #pragma unroll
    for (int half = 0; half < S / 8; ++half) {
        uint2 B[8][4];
        #pragma unroll
        for (int s = 0; s < 8; ++s) {
            #pragma unroll
            for (int t = 0; t < 4; ++t) {
                int n = nh * 32 + t * 8 + (lane >> 2);
                B[s][t] = *(const uint2*)&Bp[(half * 8 + s) * 512 + n * 8 + (lane & 3) * 2];
            }
        }
        #pragma unroll
        for (int s = 0; s < 8; ++s) {
            uint4 A0 = *(const uint4*)&Abuf[((g0 * S + half * 8 + s) * 32 + lane) * 4];
            uint4 A1 = *(const uint4*)&Abuf[(((g0 + 1) * S + half * 8 + s) * 32 + lane) * 4];
            #pragma unroll
            for (int t = 0; t < 4; ++t) {
                mma8(C[0][t][0], C[0][t][1], C[0][t][2], C[0][t][3], A0, B[s][t]);
                mma8(C[1][t][0], C[1][t][1], C[1][t][2], C[1][t][3], A1, B[s][t]);
            }
        }
    }
}

// relu(C + bias) -> tf32 -> frag-major store into dst (next GEMM's A, K-dim = cols)
template<int Sd>
static __device__ __forceinline__ void epi_store(float* __restrict__ dst,
                                                 const float C[2][4][4],
                                                 int nh, int rbase, int lane,
                                                 const float* __restrict__ bias) {
    #pragma unroll
    for (int rg = 0; rg < 2; ++rg) {
        int r0 = rbase + rg * 16 + (lane >> 2);
        #pragma unroll
        for (int t = 0; t < 4; ++t) {
            int c = nh * 32 + t * 8 + 2 * (lane & 3);
            dst[aidx(r0,     c,     Sd)] = tf32f(fmaxf(C[rg][t][0] + bias[c],     0.f));
            dst[aidx(r0,     c + 1, Sd)] = tf32f(fmaxf(C[rg][t][1] + bias[c + 1], 0.f));
            dst[aidx(r0 + 8, c,     Sd)] = tf32f(fmaxf(C[rg][t][2] + bias[c],     0.f));
            dst[aidx(r0 + 8, c + 1, Sd)] = tf32f(fmaxf(C[rg][t][3] + bias[c + 1], 0.f));
        }
    }
}

__global__ __launch_bounds__(NTHR, 1)
void uv_agg_mma(const int* __restrict__ nodes,
                const int* __restrict__ hist_uv,
                const int* __restrict__ hist_r,
                const float* __restrict__ v2e,
                const float* __restrict__ u2e,
                const float* __restrict__ r2e,
                const float* __restrict__ w1,
                const float* __restrict__ b1,
                const float* __restrict__ w2,
                const float* __restrict__ b2,
                const float* __restrict__ a1,
                const float* __restrict__ ab1,
                const float* __restrict__ a2,
                const float* __restrict__ ab2,
                const float* __restrict__ a3,
                const float* __restrict__ ab3,
                float* __restrict__ out)
{
    extern __shared__ __align__(16) float sm[];
    float* w1p  = sm + O_W1P;
    float* a1p  = sm + O_A1P;
    float* w2p  = sm + O_W2P;
    float* a2p  = sm + O_A2P;
    float* b1s  = sm + O_B1;
    float* b2s  = sm + O_B2;
    float* ab1s = sm + O_AB1;
    float* ab2s = sm + O_AB2;
    float* a3s  = sm + O_A3;
    float* r2s  = sm + O_R2S;
    float* ubS  = sm + O_UBS;
    float* bufA = sm + O_BUFA;   // frag-major, S=16 (X, then [O|U])
    float* bufB = sm + O_BUFB;   // frag-major, S=8  (X1, then H1)
    float* lgp  = sm + O_LGP;    // 2 x 128 logit partials
    float* att  = sm + O_ATT;
    float* red  = sm + O_RED;

    const int tid  = threadIdx.x;
    const int wid  = tid >> 5;
    const int lane = tid & 31;

    // ---- stage weights: pair-interleaved [s][n][j] = (w[8s+j][n], w[8s+j+4][n]) ----
    for (int i = tid; i < 8192; i += NTHR) {
        int s = i >> 9, rem = i & 511, n = rem >> 3, jj = rem & 7;
        int k = s * 8 + (jj >> 1) + 4 * (jj & 1);
        w1p[i] = tf32f(w1[k * 64 + n]);
        a1p[i] = tf32f(a1[k * 64 + n]);
    }
    for (int i = tid; i < 4096; i += NTHR) {
        int s = i >> 9, rem = i & 511, n = rem >> 3, jj = rem & 7;
        int k = s * 8 + (jj >> 1) + 4 * (jj & 1);
        w2p[i] = tf32f(w2[k * 64 + n]);
        a2p[i] = tf32f(a2[k * 64 + n]);
    }
    if (tid < 64) {
        b1s[tid]  = b1[tid];
        b2s[tid]  = b2[tid];
        ab1s[tid] = ab1[tid];
        ab2s[tid] = ab2[tid];
        a3s[tid]  = a3[tid];
    }
    for (int i = tid; i < 5 * 64; i += NTHR) r2s[i] = tf32f(r2e[i]);
    const float ab3v = ab3[0];
    __syncthreads();

    const int nh    = wid >> 2;        // N-half 0/1
    const int rbase = (wid & 3) * 32;  // 32 rows per warp
    const int g0    = (wid & 3) * 2;   // first 16-row group

    float C[2][4][4];

    for (int tile = blockIdx.x; tile < NTILES; tile += gridDim.x) {
        const int b0 = tile * 2;

        // ---- gather: X = [e_uv | e_r] into bufA (frag-major); u rows into ubS ----
        if (tid < 128) {
            int q = tid >> 6;
            ubS[q * 64 + (tid & 63)] = tf32f(u2e[(size_t)nodes[b0 + q] * 64 + (tid & 63)]);
        }
        {
            int r = tid >> 1, h = tid & 1;
            int bs = r >> 6, lraw = r & 63;
            int l = (lraw < LN) ? lraw : (LN - 1);
            if (h == 0) {
                int uv = hist_uv[(b0 + bs) * LN + l];
                const float4* vp = (const float4*)(v2e + (size_t)uv * 64);
                #pragma unroll
                for (int j = 0; j < 16; ++j) {
                    float4 f = vp[j];
                    int k = j * 4;
                    bufA[aidx(r, k + 0, 16)] = tf32f(f.x);
                    bufA[aidx(r, k + 1, 16)] = tf32f(f.y);
                    bufA[aidx(r, k + 2, 16)] = tf32f(f.z);
                    bufA[aidx(r, k + 3, 16)] = tf32f(f.w);
                }
            } else {
                int rv = hist_r[(b0 + bs) * LN + l];
                int rr = (rv > 0) ? (rv - 1) : ((rv < 0) ? (rv + 1) : 0);
                const float* rp = r2s + rr * 64;
                #pragma unroll
                for (int k = 0; k < 64; ++k)
                    bufA[aidx(r, 64 + k, 16)] = rp[k];
            }
        }
        __syncthreads();

        // ---- GEMM1: X1 = relu(X @ W1 + b1) -> bufB ; stage U into bufA[k 64..127] ----
        #pragma unroll
        for (int rg = 0; rg < 2; ++rg)
            #pragma unroll
            for (int t = 0; t < 4; ++t)
                #pragma unroll
                for (int e = 0; e < 4; ++e) C[rg][t][e] = 0.f;
        gemm_phase<16>(bufA, w1p, nh, g0, lane, C);
        epi_store<8>(bufB, C, nh, rbase, lane, b1s);
        {
            int r = tid >> 1, h = tid & 1, bs = r >> 6;
            const float* up = ubS + bs * 64;
            #pragma unroll
            for (int kk = 0; kk < 32; ++kk) {
                int k = h * 32 + kk;
                bufA[aidx(r, 64 + k, 16)] = up[k];
            }
        }
        __syncthreads();

        // ---- GEMM2: O = relu(X1 @ W2 + b2) -> bufA[k 0..63] ----
        #pragma unroll
        for (int rg = 0; rg < 2; ++rg)
            #pragma unroll
            for (int t = 0; t < 4; ++t)
                #pragma unroll
                for (int e = 0; e < 4; ++e) C[rg][t][e] = 0.f;
        gemm_phase<8>(bufB, w2p, nh, g0, lane, C);
        epi_store<16>(bufA, C, nh, rbase, lane, b2s);
        __syncthreads();

        // ---- GEMM3: H1 = relu([O|U] @ A1 + ab1) -> bufB ----
        #pragma unroll
        for (int rg = 0; rg < 2; ++rg)
            #pragma unroll
            for (int t = 0; t < 4; ++t)
                #pragma unroll
                for (int e = 0; e < 4; ++e) C[rg][t][e] = 0.f;
        gemm_phase<16>(bufA, a1p, nh, g0, lane, C);
        epi_store<8>(bufB, C, nh, rbase, lane, ab1s);
        __syncthreads();

        // ---- GEMM4: H2 = relu(H1 @ A2 + ab2); logit partials = H2 . a3 ----
        #pragma unroll
        for (int rg = 0; rg < 2; ++rg)
            #pragma unroll
            for (int t = 0; t < 4; ++t)
                #pragma unroll
                for (int e = 0; e < 4; ++e) C[rg][t][e] = 0.f;
        gemm_phase<8>(bufB, a2p, nh, g0, lane, C);
        {
            #pragma unroll
            for (int rg = 0; rg < 2; ++rg) {
                float pa = 0.f, pb = 0.f;   // rows r0, r0+8
                #pragma unroll
                for (int t = 0; t < 4; ++t) {
                    int c = nh * 32 + t * 8 + 2 * (lane & 3);
                    pa += fmaxf(C[rg][t][0] + ab2s[c],     0.f) * a3s[c];
                    pa += fmaxf(C[rg][t][1] + ab2s[c + 1], 0.f) * a3s[c + 1];
                    pb += fmaxf(C[rg][t][2] + ab2s[c],     0.f) * a3s[c];
                    pb += fmaxf(C[rg][t][3] + ab2s[c + 1], 0.f) * a3s[c + 1];
                }
                pa += __shfl_xor_sync(~0u, pa, 1); pa += __shfl_xor_sync(~0u, pa, 2);
                pb += __shfl_xor_sync(~0u, pb, 1); pb += __shfl_xor_sync(~0u, pb, 2);
                if ((lane & 3) == 0) {
                    int r0 = rbase + rg * 16 + (lane >> 2);
                    lgp[nh * 128 + r0]     = pa;
                    lgp[nh * 128 + r0 + 8] = pb;
                }
            }
        }
        __syncthreads();

        // ---- softmax over 50 (warps 0,1 -> b0,b1) ----
        if (tid < 64) {
            int w = tid >> 5, ln2 = tid & 31;
            float v1 = lgp[w * 64 + ln2] + lgp[128 + w * 64 + ln2] + ab3v;
            float v2 = (ln2 + 32 < LN)
                     ? (lgp[w * 64 + ln2 + 32] + lgp[128 + w * 64 + ln2 + 32] + ab3v)
                     : -1e30f;
            float m = fmaxf(v1, v2);
            #pragma unroll
            for (int o = 16; o; o >>= 1) m = fmaxf(m, __shfl_xor_sync(~0u, m, o));
            float e1 = expf(v1 - m);
            float e2 = (ln2 + 32 < LN) ? expf(v2 - m) : 0.f;
            float s = e1 + e2;
            #pragma unroll
            for (int o = 16; o; o >>= 1) s += __shfl_xor_sync(~0u, s, o);
            float inv = 1.f / s;
            att[w * 64 + ln2] = e1 * inv;
            if (ln2 + 32 < LN) att[w * 64 + ln2 + 32] = e2 * inv;
        }
        __syncthreads();

        // ---- aggregation: out[b,d] = sum_l O[l,d]*att[l]  (O in bufA frag layout) ----
        {
            int bs = tid >> 7, dq = tid & 127;
            int d = dq & 63, q = dq >> 6;
            float acc = 0.f;
            for (int l = q; l < LN; l += 2)
                acc += bufA[aidx(bs * 64 + l, d, 16)] * att[bs * 64 + l];
            red[tid] = acc;
        }
        __syncthreads();
        if (tid < 128) {
            int bs = tid >> 6, d = tid & 63;
            out[(size_t)(b0 + bs) * 64 + d] = red[bs * 128 + d] + red[bs * 128 + 64 + d];
        }
        __syncthreads();
    }
}

extern "C" void kernel_launch(void* const* d_in, const int* in_sizes, int n_in,
                              void* d_out, int out_size)
{
    const int*   nodes = (const int*)d_in[0];
    const int*   huv   = (const int*)d_in[1];
    const int*   hr    = (const int*)d_in[2];
    const float* v2e   = (const float*)d_in[3];
    const float* u2e   = (const float*)d_in[4];
    const float* r2e   = (const float*)d_in[5];
    const float* w1    = (const float*)d_in[6];
    const float* b1    = (const float*)d_in[7];
    const float* w2    = (const float*)d_in[8];
    const float* b2    = (const float*)d_in[9];
    const float* a1    = (const float*)d_in[10];
    const float* ab1   = (const float*)d_in[11];
    const float* a2    = (const float*)d_in[12];
    const float* ab2   = (const float*)d_in[13];
    const float* a3    = (const float*)d_in[14];
    const float* ab3   = (const float*)d_in[15];
    float* out = (float*)d_out;

    cudaFuncSetAttribute(uv_agg_mma, cudaFuncAttributeMaxDynamicSharedMemorySize, SMEM_REQ);

    uv_agg_mma<<<148, NTHR, SMEM_REQ>>>(nodes, huv, hr, v2e, u2e, r2e,
                                        w1, b1, w2, b2,
                                        a1, ab1, a2, ab2, a3, ab3, out);
}

// round 13
// speedup vs baseline: 5.8533x; 1.3428x over previous
#include <cuda_runtime.h>
#include <cstdint>

#define NB 16384
#define LN 50
#define NTILES (NB / 2)
#define NTHR 256
#define SA 132          // bufA row stride (floats), odd*4 -> conflict-free frags
#define SB 68           // bufB row stride

// smem float offsets
#define O_W1LO 0
#define O_W1HI 4096
#define O_A1LO 8192
#define O_A1HI 12288
#define O_W2LO 16384
#define O_W2HI 18432
#define O_A2LO 20480
#define O_A2HI 22528
#define O_B1   24576
#define O_B2   24640
#define O_AB1  24704
#define O_AB2  24768
#define O_A3   24832
#define O_R2S  24896
#define O_UBS  25216
#define O_BUFA 25344
#define O_BUFB 42240
#define O_LGP  50944
#define O_ATT  51200
#define O_RED  51328
#define SM_FLOATS 51584
#define SMEM_REQ (SM_FLOATS * 4)

static __device__ __forceinline__ uint32_t tf32r(float x) {
    uint32_t y; asm("cvt.rn.tf32.f32 %0, %1;" : "=r"(y) : "f"(x)); return y;
}
static __device__ __forceinline__ float tf32f(float x) {
    return __uint_as_float(tf32r(x));
}

static __device__ __forceinline__ void mma8(float C[4],
                                            uint32_t a0, uint32_t a1, uint32_t a2, uint32_t a3,
                                            uint32_t b0, uint32_t b1) {
    asm volatile(
        "mma.sync.aligned.m16n8k8.row.col.f32.tf32.tf32.f32 "
        "{%0,%1,%2,%3},{%4,%5,%6,%7},{%8,%9},{%0,%1,%2,%3};"
        : "+f"(C[0]), "+f"(C[1]), "+f"(C[2]), "+f"(C[3])
        : "r"(a0), "r"(a1), "r"(a2), "r"(a3), "r"(b0), "r"(b1));
}

// Warp tile: rows [rbase, rbase+32), cols [nh*32, nh*32+32), K = 8*S.
// A row-major (stride STRIDE), B split lo/hi arrays [s][n][q] (conflict-free).
template<int S, int STRIDE>
static __device__ __forceinline__ void gemm_phase(const float* __restrict__ Ab,
                                                  const float* __restrict__ Blo,
                                                  const float* __restrict__ Bhi,
                                                  int nh, int rbase, int lane,
                                                  float C[2][4][4]) {
    const int rq = lane >> 2, q = lane & 3;
    const float* A00 = Ab + (rbase + rq) * STRIDE + q;
    #pragma unroll
    for (int s = 0; s < S; ++s) {
        uint32_t bl[4], bh[4];
        #pragma unroll
        for (int t = 0; t < 4; ++t) {
            int nidx = s * 256 + (nh * 32 + t * 8 + rq) * 4 + q;
            bl[t] = __float_as_uint(Blo[nidx]);
            bh[t] = __float_as_uint(Bhi[nidx]);
        }
        const int k0 = 8 * s;
        uint32_t a[2][4];
        #pragma unroll
        for (int rg = 0; rg < 2; ++rg) {
            const float* Ar = A00 + rg * 16 * STRIDE;
            a[rg][0] = __float_as_uint(Ar[k0]);
            a[rg][1] = __float_as_uint(Ar[8 * STRIDE + k0]);
            a[rg][2] = __float_as_uint(Ar[k0 + 4]);
            a[rg][3] = __float_as_uint(Ar[8 * STRIDE + k0 + 4]);
        }
        #pragma unroll
        for (int rg = 0; rg < 2; ++rg)
            #pragma unroll
            for (int t = 0; t < 4; ++t)
                mma8(C[rg][t], a[rg][0], a[rg][1], a[rg][2], a[rg][3], bl[t], bh[t]);
    }
}

// relu(C + bias) -> tf32 -> row-major float2 stores
template<int STRIDE>
static __device__ __forceinline__ void epi_store(float* __restrict__ dst,
                                                 const float C[2][4][4],
                                                 int nh, int rbase, int lane,
                                                 const float* __restrict__ bias) {
    const int rq = lane >> 2, q2 = 2 * (lane & 3);
    #pragma unroll
    for (int rg = 0; rg < 2; ++rg) {
        int r0 = rbase + rg * 16 + rq;
        #pragma unroll
        for (int t = 0; t < 4; ++t) {
            int c = nh * 32 + t * 8 + q2;
            float2 v0 = {tf32f(fmaxf(C[rg][t][0] + bias[c],     0.f)),
                         tf32f(fmaxf(C[rg][t][1] + bias[c + 1], 0.f))};
            float2 v1 = {tf32f(fmaxf(C[rg][t][2] + bias[c],     0.f)),
                         tf32f(fmaxf(C[rg][t][3] + bias[c + 1], 0.f))};
            *(float2*)&dst[r0 * STRIDE + c]       = v0;
            *(float2*)&dst[(r0 + 8) * STRIDE + c] = v1;
        }
    }
}

#define CZERO(C) do { \
    _Pragma("unroll") for (int _rg = 0; _rg < 2; ++_rg) \
    _Pragma("unroll") for (int _t = 0; _t < 4; ++_t) \
    _Pragma("unroll") for (int _e = 0; _e < 4; ++_e) C[_rg][_t][_e] = 0.f; \
} while (0)

__global__ __launch_bounds__(NTHR, 1)
void uv_agg_mma(const int* __restrict__ nodes,
                const int* __restrict__ hist_uv,
                const int* __restrict__ hist_r,
                const float* __restrict__ v2e,
                const float* __restrict__ u2e,
                const float* __restrict__ r2e,
                const float* __restrict__ w1,
                const float* __restrict__ b1,
                const float* __restrict__ w2,
                const float* __restrict__ b2,
                const float* __restrict__ a1,
                const float* __restrict__ ab1,
                const float* __restrict__ a2,
                const float* __restrict__ ab2,
                const float* __restrict__ a3,
                const float* __restrict__ ab3,
                float* __restrict__ out)
{
    extern __shared__ __align__(16) float sm[];
    float* w1lo = sm + O_W1LO;
    float* w1hi = sm + O_W1HI;
    float* a1lo = sm + O_A1LO;
    float* a1hi = sm + O_A1HI;
    float* w2lo = sm + O_W2LO;
    float* w2hi = sm + O_W2HI;
    float* a2lo = sm + O_A2LO;
    float* a2hi = sm + O_A2HI;
    float* b1s  = sm + O_B1;
    float* b2s  = sm + O_B2;
    float* ab1s = sm + O_AB1;
    float* ab2s = sm + O_AB2;
    float* a3s  = sm + O_A3;
    float* r2s  = sm + O_R2S;
    float* ubS  = sm + O_UBS;
    float* bufA = sm + O_BUFA;   // 128 x SA (X = [e_uv|e_r], later [O|U])
    float* bufB = sm + O_BUFB;   // 128 x SB (X1, later H1)
    float* lgp  = sm + O_LGP;
    float* att  = sm + O_ATT;
    float* red  = sm + O_RED;

    const int tid  = threadIdx.x;
    const int wid  = tid >> 5;
    const int lane = tid & 31;

    // ---- stage weights: split lo/hi [s][n][q]: lo = W[8s+q][n], hi = W[8s+4+q][n] ----
    for (int i = tid; i < 4096; i += NTHR) {
        int s = i >> 8, n = (i >> 2) & 63, qq = i & 3;
        w1lo[i] = tf32f(w1[(8 * s + qq) * 64 + n]);
        w1hi[i] = tf32f(w1[(8 * s + 4 + qq) * 64 + n]);
        a1lo[i] = tf32f(a1[(8 * s + qq) * 64 + n]);
        a1hi[i] = tf32f(a1[(8 * s + 4 + qq) * 64 + n]);
    }
    for (int i = tid; i < 2048; i += NTHR) {
        int s = i >> 8, n = (i >> 2) & 63, qq = i & 3;
        w2lo[i] = tf32f(w2[(8 * s + qq) * 64 + n]);
        w2hi[i] = tf32f(w2[(8 * s + 4 + qq) * 64 + n]);
        a2lo[i] = tf32f(a2[(8 * s + qq) * 64 + n]);
        a2hi[i] = tf32f(a2[(8 * s + 4 + qq) * 64 + n]);
    }
    if (tid < 64) {
        b1s[tid]  = b1[tid];
        b2s[tid]  = b2[tid];
        ab1s[tid] = ab1[tid];
        ab2s[tid] = ab2[tid];
        a3s[tid]  = a3[tid];
    }
    for (int i = tid; i < 5 * 64; i += NTHR) r2s[i] = tf32f(r2e[i]);
    const float ab3v = ab3[0];
    __syncthreads();

    const int nh    = wid >> 2;
    const int rbase = (wid & 3) * 32;
    float C[2][4][4];

    for (int tile = blockIdx.x; tile < NTILES; tile += gridDim.x) {
        const int b0 = tile * 2;

        // ---- gather: u rows -> ubS; X = [e_uv | e_r] -> bufA row-major ----
        if (tid < 128) {
            int qb = tid >> 6;
            ubS[qb * 64 + (tid & 63)] = tf32f(u2e[(size_t)nodes[b0 + qb] * 64 + (tid & 63)]);
        }
        {
            int r = tid >> 1, h = tid & 1;
            int bs = r >> 6, lraw = r & 63;
            int l = (lraw < LN) ? lraw : (LN - 1);
            int uv = hist_uv[(b0 + bs) * LN + l];
            int rv = hist_r[(b0 + bs) * LN + l];
            int rr = (rv > 0) ? (rv - 1) : ((rv < 0) ? (rv + 1) : 0);
            float* dst = bufA + r * SA;
            const float4* vp = (const float4*)(v2e + (size_t)uv * 64) + h * 8;
            #pragma unroll
            for (int j = 0; j < 8; ++j) {
                float4 f = vp[j];
                float4 g = {tf32f(f.x), tf32f(f.y), tf32f(f.z), tf32f(f.w)};
                *(float4*)&dst[h * 32 + 4 * j] = g;
            }
            const float4* rp = (const float4*)(r2s + rr * 64) + h * 8;
            #pragma unroll
            for (int j = 0; j < 8; ++j)
                *(float4*)&dst[64 + h * 32 + 4 * j] = rp[j];
        }
        __syncthreads();

        // ---- GEMM1: X1 = relu(X @ W1 + b1) -> bufB ----
        CZERO(C);
        gemm_phase<16, SA>(bufA, w1lo, w1hi, nh, rbase, lane, C);
        epi_store<SB>(bufB, C, nh, rbase, lane, b1s);
        {   // stage U into bufA cols 64..127
            int r = tid >> 1, h = tid & 1, bs = r >> 6;
            const float4* up = (const float4*)(ubS + bs * 64) + h * 8;
            float* dst = bufA + r * SA + 64;
            #pragma unroll
            for (int j = 0; j < 8; ++j)
                *(float4*)&dst[h * 32 + 4 * j] = up[j];
        }
        __syncthreads();

        // ---- GEMM2: O = relu(X1 @ W2 + b2) -> bufA cols 0..63 ----
        CZERO(C);
        gemm_phase<8, SB>(bufB, w2lo, w2hi, nh, rbase, lane, C);
        epi_store<SA>(bufA, C, nh, rbase, lane, b2s);
        __syncthreads();

        // ---- GEMM3: H1 = relu([O|U] @ A1 + ab1) -> bufB ----
        CZERO(C);
        gemm_phase<16, SA>(bufA, a1lo, a1hi, nh, rbase, lane, C);
        epi_store<SB>(bufB, C, nh, rbase, lane, ab1s);
        __syncthreads();

        // ---- GEMM4: H2 = relu(H1 @ A2 + ab2); logit partials = H2 . a3 ----
        CZERO(C);
        gemm_phase<8, SB>(bufB, a2lo, a2hi, nh, rbase, lane, C);
        {
            const int rq = lane >> 2, q2 = 2 * (lane & 3);
            #pragma unroll
            for (int rg = 0; rg < 2; ++rg) {
                float pa = 0.f, pb = 0.f;
                #pragma unroll
                for (int t = 0; t < 4; ++t) {
                    int c = nh * 32 + t * 8 + q2;
                    pa += fmaxf(C[rg][t][0] + ab2s[c],     0.f) * a3s[c];
                    pa += fmaxf(C[rg][t][1] + ab2s[c + 1], 0.f) * a3s[c + 1];
                    pb += fmaxf(C[rg][t][2] + ab2s[c],     0.f) * a3s[c];
                    pb += fmaxf(C[rg][t][3] + ab2s[c + 1], 0.f) * a3s[c + 1];
                }
                pa += __shfl_xor_sync(~0u, pa, 1); pa += __shfl_xor_sync(~0u, pa, 2);
                pb += __shfl_xor_sync(~0u, pb, 1); pb += __shfl_xor_sync(~0u, pb, 2);
                if ((lane & 3) == 0) {
                    int r0 = rbase + rg * 16 + rq;
                    lgp[nh * 128 + r0]     = pa;
                    lgp[nh * 128 + r0 + 8] = pb;
                }
            }
        }
        __syncthreads();

        // ---- softmax over 50 (warps 0,1 -> b0,b1) ----
        if (tid < 64) {
            int w = tid >> 5, ln2 = tid & 31;
            float v1 = lgp[w * 64 + ln2] + lgp[128 + w * 64 + ln2] + ab3v;
            float v2 = (ln2 + 32 < LN)
                     ? (lgp[w * 64 + ln2 + 32] + lgp[128 + w * 64 + ln2 + 32] + ab3v)
                     : -1e30f;
            float m = fmaxf(v1, v2);
            #pragma unroll
            for (int o = 16; o; o >>= 1) m = fmaxf(m, __shfl_xor_sync(~0u, m, o));
            float e1 = expf(v1 - m);
            float e2 = (ln2 + 32 < LN) ? expf(v2 - m) : 0.f;
            float s = e1 + e2;
            #pragma unroll
            for (int o = 16; o; o >>= 1) s += __shfl_xor_sync(~0u, s, o);
            float inv = 1.f / s;
            att[w * 64 + ln2] = e1 * inv;
            if (ln2 + 32 < LN) att[w * 64 + ln2 + 32] = e2 * inv;
        }
        __syncthreads();

        // ---- aggregation: out[b,d] = sum_l O[l,d]*att[l] (O row-major in bufA) ----
        {
            int bs = tid >> 7, dq = tid & 127;
            int d = dq & 63, qh = dq >> 6;
            float acc = 0.f;
            for (int l = qh; l < LN; l += 2)
                acc += bufA[(bs * 64 + l) * SA + d] * att[bs * 64 + l];
            red[tid] = acc;
        }
        __syncthreads();
        if (tid < 128) {
            int bs = tid >> 6, d = tid & 63;
            out[(size_t)(b0 + bs) * 64 + d] = red[bs * 128 + d] + red[bs * 128 + 64 + d];
        }
        __syncthreads();
    }
}

extern "C" void kernel_launch(void* const* d_in, const int* in_sizes, int n_in,
                              void* d_out, int out_size)
{
    const int*   nodes = (const int*)d_in[0];
    const int*   huv   = (const int*)d_in[1];
    const int*   hr    = (const int*)d_in[2];
    const float* v2e   = (const float*)d_in[3];
    const float* u2e   = (const float*)d_in[4];
    const float* r2e   = (const float*)d_in[5];
    const float* w1    = (const float*)d_in[6];
    const float* b1    = (const float*)d_in[7];
    const float* w2    = (const float*)d_in[8];
    const float* b2    = (const float*)d_in[9];
    const float* a1    = (const float*)d_in[10];
    const float* ab1   = (const float*)d_in[11];
    const float* a2    = (const float*)d_in[12];
    const float* ab2   = (const float*)d_in[13];
    const float* a3    = (const float*)d_in[14];
    const float* ab3   = (const float*)d_in[15];
    float* out = (float*)d_out;

    cudaFuncSetAttribute(uv_agg_mma, cudaFuncAttributeMaxDynamicSharedMemorySize, SMEM_REQ);

    uv_agg_mma<<<148, NTHR, SMEM_REQ>>>(nodes, huv, hr, v2e, u2e, r2e,
                                        w1, b1, w2, b2,
                                        a1, ab1, a2, ab2, a3, ab3, out);
}